// round 10
// baseline (speedup 1.0000x reference)
#include <cuda_runtime.h>
#include <math_constants.h>

// EvenLayer min-sum check-node update — FINAL (measured optimum, R4 binary).
//
// Structure (proved in R0, rel_err = 0.0 in every round): in the reference
// mask builder, v = repeat(arange(1200),3), c = (v*3+k) % 600, and the
// lexsort((c,v)) permutation is the IDENTITY (within a variable, var*3+k
// never crosses a multiple of 600). Hence check(e) = e % 600 and the
// neighbor set of edge e is { (e%600) + 600*m : m = 0..5 } \ {e}.
// The 51.8 MB inf_mask is never read — per (batch, check): 6 loads,
// 6 exclusive sign-product / exclusive-min outputs (~245 KB total traffic
// vs >=8.6us of mask reads if done naively).
//
// Measured landscape (kernel ncu-dur): 8 blk 4.77 | 40 blk 4.06-4.45 |
// 64 blk 4.16 | 152 blk 5.06; all pipes <1% at the optimum — the kernel
// is launch-floor bound. Identical binaries produced walls of 4.61 and
// 6.50 across holds (harness-side offset); kernel dur is the stable
// metric and this shape minimizes it.
//
// Shape: grid (5, 8) x 120 threads = exact 600 checks x 8 batches, no
// bounds predicate, 12 front-batched LDGs (one exposed cold-DRAM round
// trip), strided offsets folded into LDG/STG immediates.

#define N_CHK 600
#define BATCH 8
#define E     3600
#define DEG   6

__global__ __launch_bounds__(120)
void even_layer_kernel(const float* __restrict__ x,
                       const float* __restrict__ bias,
                       float* __restrict__ out)
{
    const int c = blockIdx.x * 120 + threadIdx.x;   // check id, exact 0..599
    const int b = blockIdx.y;                        // batch id

    const int base = b * E + c;
    const float* __restrict__ xb = x + base;
    const float* __restrict__ bb = bias + c;
    float* __restrict__ ob       = out + base;

    // Front-batch ALL independent loads: 12 LDGs in flight.
    float v[DEG], bs[DEG];
#pragma unroll
    for (int m = 0; m < DEG; ++m) v[m]  = xb[m * N_CHK];
#pragma unroll
    for (int m = 0; m < DEG; ++m) bs[m] = bb[m * N_CHK];

#pragma unroll
    for (int i = 0; i < DEG; ++i) {        // exclusive reduce per edge
        float p  = 1.0f;
        float mn = CUDART_INF_F;
#pragma unroll
        for (int k = 0; k < DEG; ++k) {
            if (k != i) {
                p  = p * v[k];
                mn = fminf(mn, fabsf(v[k]));
            }
        }
        // sign() incl. sign(0)=0, matching jnp.sign(prod(...)); keep the
        // actual fp32 product (bit-XOR sign would diverge on underflow).
        const float s = (p > 0.0f) ? 1.0f : ((p < 0.0f) ? -1.0f : 0.0f);
        ob[i * N_CHK] = s * fmaxf(mn - bs[i], 0.0f);
    }
}

extern "C" void kernel_launch(void* const* d_in, const int* in_sizes, int n_in,
                              void* d_out, int out_size)
{
    // metadata order: inputs [BATCH,E] f32, bias [1,E] f32, inf_mask [E,E] f32 (unused)
    const float* x    = (const float*)d_in[0];
    const float* bias = (const float*)d_in[1];
    float* out        = (float*)d_out;

    dim3 grid(5, BATCH);                 // 5 * 120 = 600 checks, 8 batches
    even_layer_kernel<<<grid, 120>>>(x, bias, out);
}

// round 13
// speedup vs baseline: 1.4238x; 1.4238x over previous
#include <cuda_runtime.h>
#include <math_constants.h>

// EvenLayer min-sum check-node update — FINAL (measured optimum).
//
// Structure (proved in R0, rel_err = 0.0 in every round): in the reference
// mask builder, v = repeat(arange(1200),3), c = (v*3+k) % 600, and the
// lexsort((c,v)) permutation is the IDENTITY (within a variable, var*3+k
// never crosses a multiple of 600). Hence check(e) = e % 600 and the
// neighbor set of edge e is { (e%600) + 600*m : m = 0..5 } \ {e}.
// The 51.8 MB inf_mask is never read — per (batch, check): 6 loads,
// 6 exclusive sign-product / exclusive-min outputs (~245 KB total traffic
// vs >=8.6us of unavoidable DRAM time if the mask were read).
//
// Measured landscape (kernel ncu-dur): 8 blk 4.77 | 40 blk 4.19-5.28 |
// 64 blk 4.16 | 152 blk 5.06 | float4 4.90. All pipes <1% at the optimum:
// launch-envelope bound. Identical binaries span 4.19-5.28 kernel /
// 4.61-6.88 wall across holds (clock-control none) — run noise exceeds
// every remaining intra-shape effect, so this shape is final.
//
// Shape: grid (5, 8) x 120 threads = exact 600 checks x 8 batches, no
// bounds predicate, 12 front-batched LDGs (one exposed cold-DRAM round
// trip, MLP=12), strided offsets folded into LDG/STG immediates.

#define N_CHK 600
#define BATCH 8
#define E     3600
#define DEG   6

__global__ __launch_bounds__(120)
void even_layer_kernel(const float* __restrict__ x,
                       const float* __restrict__ bias,
                       float* __restrict__ out)
{
    const int c = blockIdx.x * 120 + threadIdx.x;   // check id, exact 0..599
    const int b = blockIdx.y;                        // batch id

    const int base = b * E + c;
    const float* __restrict__ xb = x + base;
    const float* __restrict__ bb = bias + c;
    float* __restrict__ ob       = out + base;

    // Front-batch ALL independent loads: 12 LDGs in flight.
    float v[DEG], bs[DEG];
#pragma unroll
    for (int m = 0; m < DEG; ++m) v[m]  = xb[m * N_CHK];
#pragma unroll
    for (int m = 0; m < DEG; ++m) bs[m] = bb[m * N_CHK];

#pragma unroll
    for (int i = 0; i < DEG; ++i) {        // exclusive reduce per edge
        float p  = 1.0f;
        float mn = CUDART_INF_F;
#pragma unroll
        for (int k = 0; k < DEG; ++k) {
            if (k != i) {
                p  = p * v[k];
                mn = fminf(mn, fabsf(v[k]));
            }
        }
        // sign() incl. sign(0)=0, matching jnp.sign(prod(...)); keep the
        // actual fp32 product (bit-XOR sign would diverge on underflow).
        const float s = (p > 0.0f) ? 1.0f : ((p < 0.0f) ? -1.0f : 0.0f);
        ob[i * N_CHK] = s * fmaxf(mn - bs[i], 0.0f);
    }
}

extern "C" void kernel_launch(void* const* d_in, const int* in_sizes, int n_in,
                              void* d_out, int out_size)
{
    // metadata order: inputs [BATCH,E] f32, bias [1,E] f32, inf_mask [E,E] f32 (unused)
    const float* x    = (const float*)d_in[0];
    const float* bias = (const float*)d_in[1];
    float* out        = (float*)d_out;

    dim3 grid(5, BATCH);                 // 5 * 120 = 600 checks, 8 batches
    even_layer_kernel<<<grid, 120>>>(x, bias, out);
}